// round 16
// baseline (speedup 1.0000x reference)
#include <cuda_runtime.h>

// Stacked depth-3 tanh RNN — 12-CTA cluster per batch-pair, systolic wavefront
// with DEPENDENCY-SPLIT barriers. B=16, T=2048, H=256, DEPTH=3.
// Cluster (4,3,1): rank = cid + 4*layer. Iteration i: layer k computes t=i-k.
// Barriers (all ping-pong, parity=(phase>>1)&1):
//   mb_up: upstream output pushes (tx 2048B) + self expect (count 1)
//   mb_h : peer h pushes (tx 1536B) + self expect (count 1)
//   mb_bp: read-done arrives from push-target CTAs, per-warp (count 8*targets)
// Staged waits: up-wait -> upstream FFMA -> h-wait -> peer FFMA -> bp arrives
// -> reduce/tanh -> bp-wait(fast) -> st.async pushes. All slots indexed by
// ITERATION parity; loop unrolled x2 so every offset is a constant.

#define H_DIM 256
#define DEPTH 3
#define NTHREADS 256

typedef unsigned long long ull;

__device__ __forceinline__ void ffma2(ull& d, ull a, ull b) {
    asm("fma.rn.f32x2 %0, %1, %2, %0;" : "+l"(d) : "l"(a), "l"(b));
}
__device__ __forceinline__ float lo32(ull v) { return __uint_as_float((unsigned)v); }
__device__ __forceinline__ float hi32(ull v) { return __uint_as_float((unsigned)(v >> 32)); }

__device__ __forceinline__ unsigned smem_u32(const void* p) {
    return (unsigned)__cvta_generic_to_shared(p);
}
__device__ __forceinline__ unsigned mapa_addr(unsigned laddr, int rank) {
    unsigned ra;
    asm volatile("mapa.shared::cluster.u32 %0, %1, %2;" : "=r"(ra) : "r"(laddr), "r"(rank));
    return ra;
}
__device__ __forceinline__ void mbar_init(unsigned mb, int cnt) {
    asm volatile("mbarrier.init.shared.b64 [%0], %1;" :: "r"(mb), "r"(cnt) : "memory");
}
__device__ __forceinline__ void mbar_wait(unsigned mb, int parity) {
    asm volatile(
        "{\n\t"
        ".reg .pred P;\n\t"
        "WL_%=:\n\t"
        "mbarrier.try_wait.parity.acquire.cluster.shared::cta.b64 P, [%0], %1, 0x989680;\n\t"
        "@P bra.uni WD_%=;\n\t"
        "bra.uni WL_%=;\n\t"
        "WD_%=:\n\t"
        "}" :: "r"(mb), "r"(parity) : "memory");
}
__device__ __forceinline__ void arrive_mapped(unsigned addr) {
    asm volatile("mbarrier.arrive.release.cluster.shared::cluster.b64 _, [%0];"
                 :: "r"(addr) : "memory");
}
__device__ __forceinline__ void mbar_expect_arrive(unsigned mb, unsigned bytes) {
    asm volatile("mbarrier.arrive.expect_tx.shared.b64 _, [%0], %1;"
                 :: "r"(mb), "r"(bytes) : "memory");
}
__device__ __forceinline__ void mbar_arrive_local(unsigned mb) {
    asm volatile("mbarrier.arrive.shared.b64 _, [%0];" :: "r"(mb) : "memory");
}
__device__ __forceinline__ void st_async_f32(unsigned dst, float v, unsigned mbar) {
    asm volatile("st.async.shared::cluster.mbarrier::complete_tx::bytes.b32 [%0], %1, [%2];"
                 :: "r"(dst), "r"(__float_as_uint(v)), "r"(mbar) : "memory");
}
__device__ __forceinline__ float fast_tanh(float z) {
    const float e = __expf(z + z);
    return 1.0f - __fdividef(2.0f, e + 1.0f);
}

__global__ void __launch_bounds__(NTHREADS, 1) __cluster_dims__(4, 3, 1)
rnn12_kernel(const float* __restrict__ x,
             const int*   __restrict__ seq_lens,
             const float* __restrict__ W_ih,
             const float* __restrict__ W_hh,
             const float* __restrict__ bias,
             float* out,
             int T) {
    __shared__ float in_s[2][2][256];   // layer-0 x ring, slot = t&1
    __shared__ float hrecv[2][2][256];  // slot = i&1 (producer iteration parity)
    __shared__ float irecv[2][2][256];  // slot = i&1 of the CONSUMER's read phase
    __shared__ __align__(8) ull mb_h[2], mb_up[2], mb_bp[2];

    const int cid   = blockIdx.x & 3;
    const int p     = blockIdx.x >> 2;
    const int layer = blockIdx.y;

    const int tid  = threadIdx.x;
    const int w    = tid >> 5;
    const int lane = tid & 31;
    const int n_base = cid * 64 + w * 8;

    const unsigned mbh = smem_u32(&mb_h[0]);
    const unsigned mbu = smem_u32(&mb_up[0]);
    const unsigned mbb = smem_u32(&mb_bp[0]);
    const int bp_count = 8 * ((layer < DEPTH - 1) ? 7 : 3);
    if (tid == 0) {
        mbar_init(mbh, 1);     mbar_init(mbh + 8, 1);
        mbar_init(mbu, 1);     mbar_init(mbu + 8, 1);
        mbar_init(mbb, bp_count); mbar_init(mbb + 8, bp_count);
    }
    for (int idx = tid; idx < 2 * 2 * 256; idx += NTHREADS) {
        ((float*)hrecv)[idx] = 0.0f;
        ((float*)irecv)[idx] = 0.0f;
    }
    __syncthreads();
    asm volatile("barrier.cluster.arrive.aligned;" ::: "memory");
    asm volatile("barrier.cluster.wait.aligned;" ::: "memory");

    // bp arrive target for this lane (per-warp arrives): lanes 0..2 -> peers,
    // lanes 3..6 -> upstream quad (layers>0 only).
    const int nbp_send = (layer > 0) ? 7 : 3;
    unsigned bp_t = 0;
    if (lane < nbp_send) {
        const int rk = (lane < 3) ? (((cid + 1 + lane) & 3) + 4 * layer)
                                  : ((lane - 3) + 4 * (layer - 1));
        bp_t = mapa_addr(mbb, rk);
    }

    // ---- weights: input chunks j=0..3 in slots 0..3; W_hh permuted by cid
    //      (slot 4 = own chunk, slots 5..7 = peers (cid+1..3)&3)
    ull Wr[8][8];
    {
        const float* wih = W_ih + layer * H_DIM * H_DIM;
        const float* whh = W_hh + layer * H_DIM * H_DIM;
#pragma unroll
        for (int i = 0; i < 8; i++) {
            const int n = n_base + i;
#pragma unroll
            for (int j = 0; j < 4; j++)
                Wr[i][j] = *(const ull*)(wih + n * 256 + (j * 32 + lane) * 2);
#pragma unroll
            for (int jj = 0; jj < 4; jj++) {
                const int c = (cid + jj) & 3;
                Wr[i][4 + jj] = *(const ull*)(whh + n * 256 + (c * 32 + lane) * 2);
            }
        }
    }

    // local read bases (ull units; slot stride 256, batch stride 128)
    const ull* hb = (const ull*)hrecv;
    const ull* ib = (const ull*)irecv;
    const int o_own = cid * 32 + lane;
    const int o_pk1 = ((cid + 1) & 3) * 32 + lane;
    const int o_pk2 = ((cid + 2) & 3) * 32 + lane;
    const int o_pk3 = ((cid + 3) & 3) * 32 + lane;

    // ---- writer lanes
    const bool active_lane = (lane & 1) == 0;
    float  bias_v = 0.0f;
    int    len_v  = -1;
    float* outp   = out;
    float* hown   = 0;
    unsigned hpd[3], hpm[3], ipd[4], ipm[4];
    if (active_lane) {
        const int bl = lane >> 4;
        const int m  = ((lane >> 3) & 1) * 4 + ((lane >> 2) & 1) * 2 + ((lane >> 1) & 1);
        const int nr = n_base + m;
        const int bg = 2 * p + bl;
        bias_v = bias[layer * H_DIM + nr];
        len_v  = seq_lens[bg];
        outp   = out + (((size_t)bg * T) * DEPTH + layer) * H_DIM + nr;
        hown   = &hrecv[0][bl][nr];
        const unsigned off = (unsigned)(bl * 1024 + nr * 4);
        const unsigned hrb = smem_u32(&hrecv[0][0][0]);
        const unsigned irb = smem_u32(&irecv[0][0][0]);
#pragma unroll
        for (int jj = 0; jj < 3; jj++) {
            const int r = ((cid + 1 + jj) & 3) + 4 * layer;
            hpd[jj] = mapa_addr(hrb, r) + off;
            hpm[jj] = mapa_addr(mbh, r);
        }
        if (layer < DEPTH - 1) {
#pragma unroll
            for (int q = 0; q < 4; q++) {
                const int r = q + 4 * (layer + 1);
                ipd[q] = mapa_addr(irb, r) + off;
                ipm[q] = mapa_addr(mbu, r);
            }
        }
    }

    // ---- layer-0 loaders
    const bool loader = (layer == 0) && (tid < 128);
    const float* in_ptr = 0;
    int s_bl = 0, s_c4 = 0;
    if (loader) {
        s_bl = tid >> 6;
        s_c4 = (tid & 63) << 2;
        in_ptr = x + ((size_t)(2 * p + s_bl) * T) * H_DIM + s_c4;
        *(float4*)&in_s[0][s_bl][s_c4] = *(const float4*)in_ptr;
        *(float4*)&in_s[1][s_bl][s_c4] = *(const float4*)(in_ptr + H_DIM);
        in_ptr += 2 * H_DIM;
    }
    float4 pf_cur = make_float4(0.f, 0.f, 0.f, 0.f);
    __syncthreads();

    int pm = 0;     // (i>>1)&1 for the current pair

#define ITER(I, P, PAR) do {                                                   \
    const int t_ = (I) - layer;                                                \
    const bool act_ = (t_ >= 0) && (t_ < T);                                   \
    ull a0[8], a1[8];                                                          \
    _Pragma("unroll") for (int q = 0; q < 8; q++) { a0[q] = 0; a1[q] = 0; }    \
    float4 pfn_; const bool iss_ = loader && (I) + 2 < T;                      \
    if (iss_) { pfn_ = *(const float4*)in_ptr; in_ptr += H_DIM; }              \
    if (act_) {                                                                \
        const ull o0 = hb[((P)^1) * 256 + o_own];                              \
        const ull o1 = hb[((P)^1) * 256 + 128 + o_own];                        \
        _Pragma("unroll") for (int q = 0; q < 8; q++) {                        \
            ffma2(a0[q], o0, Wr[q][4]); ffma2(a1[q], o1, Wr[q][4]); }          \
        if (layer == 0) {                                                      \
            const ull* i0 = (const ull*)in_s[(P)][0];                          \
            const ull* i1 = (const ull*)in_s[(P)][1];                          \
            _Pragma("unroll") for (int j = 0; j < 4; j++) {                    \
                const ull b0 = i0[j * 32 + lane];                              \
                const ull b1 = i1[j * 32 + lane];                              \
                _Pragma("unroll") for (int q = 0; q < 8; q++) {                \
                    ffma2(a0[q], b0, Wr[q][j]); ffma2(a1[q], b1, Wr[q][j]); }  \
            }                                                                  \
        }                                                                      \
    }                                                                          \
    if ((I) <= T && tid == 0) {                                                \
        const int tn_ = t_ + 1;                                                \
        const unsigned eh_ = (tn_ >= 1 && tn_ <= T - 1) ? 1536u : 0u;          \
        if (eh_) mbar_expect_arrive(mbh + 8u * (P), eh_);                      \
        else     mbar_arrive_local(mbh + 8u * (P));                            \
        if (layer > 0) {                                                       \
            const unsigned eu_ = (tn_ >= 0 && tn_ <= T - 1) ? 2048u : 0u;      \
            if (eu_) mbar_expect_arrive(mbu + 8u * (P), eu_);                  \
            else     mbar_arrive_local(mbu + 8u * (P));                        \
        }                                                                      \
    }                                                                          \
    if (layer > 0) {                                                           \
        if ((I) > 0) mbar_wait(mbu + 8u * ((P)^1), (PAR));                     \
        if (act_) {                                                            \
            _Pragma("unroll") for (int j = 0; j < 4; j++) {                    \
                const ull b0 = ib[((P)^1) * 256 + j * 32 + lane];              \
                const ull b1 = ib[((P)^1) * 256 + 128 + j * 32 + lane];        \
                _Pragma("unroll") for (int q = 0; q < 8; q++) {                \
                    ffma2(a0[q], b0, Wr[q][j]); ffma2(a1[q], b1, Wr[q][j]); }  \
            }                                                                  \
        }                                                                      \
    }                                                                          \
    if (loader && (I) >= 1 && (I) + 1 < T)                                     \
        *(float4*)&in_s[(P)^1][s_bl][s_c4] = pf_cur;                           \
    if (iss_) pf_cur = pfn_;                                                   \
    if ((I) > 0) mbar_wait(mbh + 8u * ((P)^1), (PAR));                         \
    if (act_) {                                                                \
        const ull h10 = hb[((P)^1) * 256 + o_pk1], h11 = hb[((P)^1) * 256 + 128 + o_pk1]; \
        const ull h20 = hb[((P)^1) * 256 + o_pk2], h21 = hb[((P)^1) * 256 + 128 + o_pk2]; \
        const ull h30 = hb[((P)^1) * 256 + o_pk3], h31 = hb[((P)^1) * 256 + 128 + o_pk3]; \
        _Pragma("unroll") for (int q = 0; q < 8; q++) {                        \
            ffma2(a0[q], h10, Wr[q][5]); ffma2(a1[q], h11, Wr[q][5]);          \
            ffma2(a0[q], h20, Wr[q][6]); ffma2(a1[q], h21, Wr[q][6]);          \
            ffma2(a0[q], h30, Wr[q][7]); ffma2(a1[q], h31, Wr[q][7]); }        \
    }                                                                          \
    if ((I) <= T && lane < nbp_send) arrive_mapped(bp_t + 8u * (P));           \
    float v_ = 0.0f;                                                           \
    if (act_) {                                                                \
        float k_[8];                                                           \
        {                                                                      \
            float s0_[8], s1_[8];                                              \
            _Pragma("unroll") for (int q = 0; q < 8; q++) {                    \
                s0_[q] = lo32(a0[q]) + hi32(a0[q]);                            \
                s1_[q] = lo32(a1[q]) + hi32(a1[q]); }                          \
            const bool b4 = (lane & 16) != 0;                                  \
            _Pragma("unroll") for (int m_ = 0; m_ < 8; m_++) {                 \
                const float aa = b4 ? s1_[m_] : s0_[m_];                       \
                const float bb = b4 ? s0_[m_] : s1_[m_];                       \
                k_[m_] = aa + __shfl_xor_sync(0xffffffffu, bb, 16); }          \
        }                                                                      \
        { const bool b3 = (lane & 8) != 0;                                     \
          _Pragma("unroll") for (int q = 0; q < 4; q++) {                      \
            const float aa = b3 ? k_[q + 4] : k_[q];                           \
            const float bb = b3 ? k_[q] : k_[q + 4];                           \
            k_[q] = aa + __shfl_xor_sync(0xffffffffu, bb, 8); } }              \
        { const bool b2 = (lane & 4) != 0;                                     \
          _Pragma("unroll") for (int q = 0; q < 2; q++) {                      \
            const float aa = b2 ? k_[q + 2] : k_[q];                           \
            const float bb = b2 ? k_[q] : k_[q + 2];                           \
            k_[q] = aa + __shfl_xor_sync(0xffffffffu, bb, 4); } }              \
        { const bool b1 = (lane & 2) != 0;                                     \
          const float aa = b1 ? k_[1] : k_[0];                                 \
          const float bb = b1 ? k_[0] : k_[1];                                 \
          k_[0] = aa + __shfl_xor_sync(0xffffffffu, bb, 2); }                  \
        k_[0] += __shfl_xor_sync(0xffffffffu, k_[0], 1);                       \
        if (active_lane) {                                                     \
            v_ = fast_tanh(k_[0] + bias_v);                                    \
            if (t_ >= len_v) v_ = 0.0f;                                        \
            *outp = v_;                                                        \
            outp += DEPTH * H_DIM;                                             \
            hown[(P) * 512] = v_;                                              \
        }                                                                      \
    }                                                                          \
    if ((I) > 0) mbar_wait(mbb + 8u * ((P)^1), (PAR));                         \
    if (act_ && active_lane) {                                                 \
        if (t_ <= T - 2) {                                                     \
            _Pragma("unroll") for (int jj = 0; jj < 3; jj++)                   \
                st_async_f32(hpd[jj] + (P) * 2048u, v_, hpm[jj] + (P) * 8u);   \
        }                                                                      \
        if (layer < DEPTH - 1) {                                               \
            _Pragma("unroll") for (int q = 0; q < 4; q++)                      \
                st_async_f32(ipd[q] + (P) * 2048u, v_, ipm[q] + (P) * 8u);     \
        }                                                                      \
    }                                                                          \
    __syncthreads();                                                           \
} while (0)

    for (int i2 = 0; i2 <= T; i2 += 2) {
        ITER(i2,     0, pm ^ 1);
        ITER(i2 + 1, 1, pm);
        pm ^= 1;
    }
#undef ITER

    // terminal: no CTA exits while peers may still push/arrive into it
    asm volatile("barrier.cluster.arrive.aligned;" ::: "memory");
    asm volatile("barrier.cluster.wait.aligned;" ::: "memory");
}

extern "C" void kernel_launch(void* const* d_in, const int* in_sizes, int n_in,
                              void* d_out, int out_size) {
    const float* x    = (const float*)d_in[0];
    const int*   seq  = (const int*)  d_in[1];
    const float* W_ih = (const float*)d_in[2];
    const float* W_hh = (const float*)d_in[3];
    const float* bias = (const float*)d_in[4];
    float* out = (float*)d_out;

    const int B = in_sizes[1];                    // 16
    const int T = in_sizes[0] / (B * H_DIM);      // 2048

    cudaFuncSetAttribute(rnn12_kernel,
                         cudaFuncAttributeNonPortableClusterSizeAllowed, 1);

    rnn12_kernel<<<dim3((B / 2) * 4, DEPTH, 1), NTHREADS>>>(x, seq, W_ih, W_hh, bias, out, T);
}

// round 17
// speedup vs baseline: 1.1076x; 1.1076x over previous
#include <cuda_runtime.h>

// Stacked depth-3 tanh RNN — 12-CTA cluster per batch-pair, systolic lockstep,
// ST.ASYNC PUSH exchange (R15 protocol, proven), UNROLLED x2 so all parity-
// dependent offsets are compile-time-resolved. B=16, T=2048, H=256, DEPTH=3.
// Cluster (4,3,1): rank = cid + 4*layer. Iteration i: layer k computes t=i-k.
// One ping-pong barrier per phase: 13 arrivals (12 lockstep + 1 self
// arrive.expect_tx) + exact tx bytes from st.async pushes.

#define H_DIM 256
#define DEPTH 3
#define NTHREADS 256
#define CL_SZ 12
#define MB_COUNT 13

typedef unsigned long long ull;

__device__ __forceinline__ void ffma2(ull& d, ull a, ull b) {
    asm("fma.rn.f32x2 %0, %1, %2, %0;" : "+l"(d) : "l"(a), "l"(b));
}
__device__ __forceinline__ float lo32(ull v) { return __uint_as_float((unsigned)v); }
__device__ __forceinline__ float hi32(ull v) { return __uint_as_float((unsigned)(v >> 32)); }

__device__ __forceinline__ unsigned smem_u32(const void* p) {
    return (unsigned)__cvta_generic_to_shared(p);
}
__device__ __forceinline__ unsigned mapa_addr(unsigned laddr, int rank) {
    unsigned ra;
    asm volatile("mapa.shared::cluster.u32 %0, %1, %2;" : "=r"(ra) : "r"(laddr), "r"(rank));
    return ra;
}
__device__ __forceinline__ void mbar_init(unsigned mb, int cnt) {
    asm volatile("mbarrier.init.shared.b64 [%0], %1;" :: "r"(mb), "r"(cnt) : "memory");
}
__device__ __forceinline__ void mbar_wait(unsigned mb, int parity) {
    asm volatile(
        "{\n\t"
        ".reg .pred P;\n\t"
        "WL_%=:\n\t"
        "mbarrier.try_wait.parity.acquire.cluster.shared::cta.b64 P, [%0], %1, 0x989680;\n\t"
        "@P bra.uni WD_%=;\n\t"
        "bra.uni WL_%=;\n\t"
        "WD_%=:\n\t"
        "}" :: "r"(mb), "r"(parity) : "memory");
}
__device__ __forceinline__ void arrive_mapped(unsigned addr) {
    asm volatile("mbarrier.arrive.release.cluster.shared::cluster.b64 _, [%0];"
                 :: "r"(addr) : "memory");
}
__device__ __forceinline__ void mbar_expect_arrive(unsigned mb, unsigned bytes) {
    asm volatile("mbarrier.arrive.expect_tx.shared.b64 _, [%0], %1;"
                 :: "r"(mb), "r"(bytes) : "memory");
}
__device__ __forceinline__ void mbar_arrive_local(unsigned mb) {
    asm volatile("mbarrier.arrive.shared.b64 _, [%0];" :: "r"(mb) : "memory");
}
__device__ __forceinline__ void st_async_f32(unsigned dst, float v, unsigned mbar) {
    asm volatile("st.async.shared::cluster.mbarrier::complete_tx::bytes.b32 [%0], %1, [%2];"
                 :: "r"(dst), "r"(__float_as_uint(v)), "r"(mbar) : "memory");
}
__device__ __forceinline__ float fast_tanh(float z) {
    const float e = __expf(z + z);
    return 1.0f - __fdividef(2.0f, e + 1.0f);
}

__global__ void __launch_bounds__(NTHREADS, 1) __cluster_dims__(4, 3, 1)
rnn12_kernel(const float* __restrict__ x,
             const int*   __restrict__ seq_lens,
             const float* __restrict__ W_ih,
             const float* __restrict__ W_hh,
             const float* __restrict__ bias,
             float* out,
             int T) {
    __shared__ float in_s[2][2][256];   // layer-0 x ring, slot = i&1
    __shared__ float hrecv[2][2][256];  // [slot t&1][batch][n]: own STS + peer pushes
    __shared__ float irecv[2][2][256];  // [slot t&1][batch][n]: upstream pushes
    __shared__ __align__(8) ull mbar[2];

    const int cid   = blockIdx.x & 3;
    const int p     = blockIdx.x >> 2;
    const int layer = blockIdx.y;
    const int lp    = layer & 1;

    const int tid  = threadIdx.x;
    const int w    = tid >> 5;
    const int lane = tid & 31;
    const int n_base = cid * 64 + w * 8;

    const unsigned mb0 = smem_u32(&mbar[0]);
    if (tid == 0) { mbar_init(mb0, MB_COUNT); mbar_init(mb0 + 8, MB_COUNT); }
    for (int idx = tid; idx < 2 * 2 * 256; idx += NTHREADS) {
        ((float*)hrecv)[idx] = 0.0f;
        ((float*)irecv)[idx] = 0.0f;
    }
    __syncthreads();
    asm volatile("barrier.cluster.arrive.aligned;" ::: "memory");
    asm volatile("barrier.cluster.wait.aligned;" ::: "memory");

    unsigned ab = 0;
    if (tid < CL_SZ) ab = mapa_addr(mb0, tid);

    const unsigned hrb = smem_u32(&hrecv[0][0][0]);
    const unsigned irb = smem_u32(&irecv[0][0][0]);

    // ---- parity-resolved loop-invariant offsets.
    //      ps(i) = (t+1)&1 = (P+layer+1)&1 ; ts(i) = t&1 = (P+layer)&1
    const int psO0 = (lp ^ 1) * 256, psO1 = lp * 256;          // ull idx, h slot read
    const int tsI0 = lp * 256,       tsI1 = (lp ^ 1) * 256;    // ull idx, irecv read
    const unsigned tsB0 = (unsigned)lp * 2048u,  tsB1 = (unsigned)(lp ^ 1) * 2048u; // push byte off
    const int tsH0 = lp * 512,       tsH1 = (lp ^ 1) * 512;    // hown float idx

    // ---- weights: input chunks j=0..3 in slots 0..3; W_hh permuted by cid
    ull Wr[8][8];
    {
        const float* wih = W_ih + layer * H_DIM * H_DIM;
        const float* whh = W_hh + layer * H_DIM * H_DIM;
#pragma unroll
        for (int i = 0; i < 8; i++) {
            const int n = n_base + i;
#pragma unroll
            for (int j = 0; j < 4; j++)
                Wr[i][j] = *(const ull*)(wih + n * 256 + (j * 32 + lane) * 2);
#pragma unroll
            for (int jj = 0; jj < 4; jj++) {
                const int c = (cid + jj) & 3;
                Wr[i][4 + jj] = *(const ull*)(whh + n * 256 + (c * 32 + lane) * 2);
            }
        }
    }

    const ull* hb = (const ull*)hrecv;
    const ull* ib = (const ull*)irecv;
    const int o_own = cid * 32 + lane;
    const int o_pk1 = ((cid + 1) & 3) * 32 + lane;
    const int o_pk2 = ((cid + 2) & 3) * 32 + lane;
    const int o_pk3 = ((cid + 3) & 3) * 32 + lane;

    // ---- writer lanes
    const bool active_lane = (lane & 1) == 0;
    float  bias_v = 0.0f;
    int    len_v  = -1;
    float* outp   = out;
    float* hown   = 0;
    unsigned hpd[3], hpm[3], ipd[4], ipm[4];
    if (active_lane) {
        const int bl = lane >> 4;
        const int m  = ((lane >> 3) & 1) * 4 + ((lane >> 2) & 1) * 2 + ((lane >> 1) & 1);
        const int nr = n_base + m;
        const int bg = 2 * p + bl;
        bias_v = bias[layer * H_DIM + nr];
        len_v  = seq_lens[bg];
        outp   = out + (((size_t)bg * T) * DEPTH + layer) * H_DIM + nr;
        hown   = &hrecv[0][bl][nr];
        const unsigned off = (unsigned)(bl * 1024 + nr * 4);
#pragma unroll
        for (int jj = 0; jj < 3; jj++) {
            const int r = ((cid + 1 + jj) & 3) + 4 * layer;
            hpd[jj] = mapa_addr(hrb, r) + off;
            hpm[jj] = mapa_addr(mb0, r);
        }
        if (layer < DEPTH - 1) {
#pragma unroll
            for (int q = 0; q < 4; q++) {
                const int r = q + 4 * (layer + 1);
                ipd[q] = mapa_addr(irb, r) + off;
                ipm[q] = mapa_addr(mb0, r);
            }
        }
    }

    // ---- layer-0 loaders: LDG issued 1 iteration before commit
    const bool loader = (layer == 0) && (tid < 128);
    const float* in_ptr = 0;
    int s_bl = 0, s_c4 = 0;
    if (loader) {
        s_bl = tid >> 6;
        s_c4 = (tid & 63) << 2;
        in_ptr = x + ((size_t)(2 * p + s_bl) * T) * H_DIM + s_c4;
        *(float4*)&in_s[0][s_bl][s_c4] = *(const float4*)in_ptr;           // t=0
        *(float4*)&in_s[1][s_bl][s_c4] = *(const float4*)(in_ptr + H_DIM); // t=1
        in_ptr += 2 * H_DIM;                    // -> x[2]
    }
    float4 pf_cur = make_float4(0.f, 0.f, 0.f, 0.f);
    __syncthreads();

    int pm = 0;   // (i>>1)&1 for the current pair

#define ITER(I, P, PAR) do {                                                   \
    const int t_ = (I) - layer;                                                \
    const bool act_ = (t_ >= 0) && (t_ < T);                                   \
    const int psO_ = (P) ? psO1 : psO0;                                        \
    const int tsI_ = (P) ? tsI1 : tsI0;                                        \
    const unsigned tsB_ = (P) ? tsB1 : tsB0;                                   \
    const int tsH_ = (P) ? tsH1 : tsH0;                                        \
    ull a0[8], a1[8];                                                          \
    _Pragma("unroll") for (int q = 0; q < 8; q++) { a0[q] = 0; a1[q] = 0; }    \
    float4 pfn_; const bool iss_ = loader && (I) + 2 < T;                      \
    if (iss_) { pfn_ = *(const float4*)in_ptr; in_ptr += H_DIM; }              \
    if (act_) {                                                                \
        const ull o0 = hb[psO_ + o_own];                                       \
        const ull o1 = hb[psO_ + 128 + o_own];                                 \
        _Pragma("unroll") for (int q = 0; q < 8; q++) {                        \
            ffma2(a0[q], o0, Wr[q][4]); ffma2(a1[q], o1, Wr[q][4]); }          \
        if (layer == 0) {                                                      \
            const ull* i0 = (const ull*)in_s[(P)][0];                          \
            const ull* i1 = (const ull*)in_s[(P)][1];                          \
            _Pragma("unroll") for (int j = 0; j < 4; j++) {                    \
                const ull b0 = i0[j * 32 + lane];                              \
                const ull b1 = i1[j * 32 + lane];                              \
                _Pragma("unroll") for (int q = 0; q < 8; q++) {                \
                    ffma2(a0[q], b0, Wr[q][j]); ffma2(a1[q], b1, Wr[q][j]); }  \
            }                                                                  \
        }                                                                      \
    }                                                                          \
    if ((I) > 0) mbar_wait(mb0 + 8u * ((P) ^ 1), (PAR));                       \
    if ((I) <= T && tid == 0) {                                                \
        const int tn_ = t_ + 1;                                                \
        unsigned e_ = 0;                                                       \
        if (t_ >= 0 && t_ <= T - 2) e_ += 1536u;                               \
        if (layer > 0 && tn_ >= 0 && tn_ <= T - 1) e_ += 2048u;                \
        const unsigned mbi_ = mb0 + 8u * (P);                                  \
        if (e_) mbar_expect_arrive(mbi_, e_); else mbar_arrive_local(mbi_);    \
    }                                                                          \
    if (loader && (I) >= 1 && (I) + 1 < T)                                     \
        *(float4*)&in_s[(P) ^ 1][s_bl][s_c4] = pf_cur;                         \
    if (iss_) pf_cur = pfn_;                                                   \
    if (act_) {                                                                \
        if (layer > 0) {                                                       \
            _Pragma("unroll") for (int j = 0; j < 4; j++) {                    \
                const ull b0 = ib[tsI_ + j * 32 + lane];                       \
                const ull b1 = ib[tsI_ + 128 + j * 32 + lane];                 \
                _Pragma("unroll") for (int q = 0; q < 8; q++) {                \
                    ffma2(a0[q], b0, Wr[q][j]); ffma2(a1[q], b1, Wr[q][j]); }  \
            }                                                                  \
        }                                                                      \
        {                                                                      \
            const ull h10 = hb[psO_ + o_pk1], h11 = hb[psO_ + 128 + o_pk1];    \
            const ull h20 = hb[psO_ + o_pk2], h21 = hb[psO_ + 128 + o_pk2];    \
            const ull h30 = hb[psO_ + o_pk3], h31 = hb[psO_ + 128 + o_pk3];    \
            _Pragma("unroll") for (int q = 0; q < 8; q++) {                    \
                ffma2(a0[q], h10, Wr[q][5]); ffma2(a1[q], h11, Wr[q][5]);      \
                ffma2(a0[q], h20, Wr[q][6]); ffma2(a1[q], h21, Wr[q][6]);      \
                ffma2(a0[q], h30, Wr[q][7]); ffma2(a1[q], h31, Wr[q][7]); }    \
        }                                                                      \
        float k_[8];                                                           \
        {                                                                      \
            float s0_[8], s1_[8];                                              \
            _Pragma("unroll") for (int q = 0; q < 8; q++) {                    \
                s0_[q] = lo32(a0[q]) + hi32(a0[q]);                            \
                s1_[q] = lo32(a1[q]) + hi32(a1[q]); }                          \
            const bool b4 = (lane & 16) != 0;                                  \
            _Pragma("unroll") for (int m_ = 0; m_ < 8; m_++) {                 \
                const float aa = b4 ? s1_[m_] : s0_[m_];                       \
                const float bb = b4 ? s0_[m_] : s1_[m_];                       \
                k_[m_] = aa + __shfl_xor_sync(0xffffffffu, bb, 16); }          \
        }                                                                      \
        { const bool b3 = (lane & 8) != 0;                                     \
          _Pragma("unroll") for (int q = 0; q < 4; q++) {                      \
            const float aa = b3 ? k_[q + 4] : k_[q];                           \
            const float bb = b3 ? k_[q] : k_[q + 4];                           \
            k_[q] = aa + __shfl_xor_sync(0xffffffffu, bb, 8); } }              \
        { const bool b2 = (lane & 4) != 0;                                     \
          _Pragma("unroll") for (int q = 0; q < 2; q++) {                      \
            const float aa = b2 ? k_[q + 2] : k_[q];                           \
            const float bb = b2 ? k_[q] : k_[q + 2];                           \
            k_[q] = aa + __shfl_xor_sync(0xffffffffu, bb, 4); } }              \
        { const bool b1 = (lane & 2) != 0;                                     \
          const float aa = b1 ? k_[1] : k_[0];                                 \
          const float bb = b1 ? k_[0] : k_[1];                                 \
          k_[0] = aa + __shfl_xor_sync(0xffffffffu, bb, 2); }                  \
        k_[0] += __shfl_xor_sync(0xffffffffu, k_[0], 1);                       \
        if (active_lane) {                                                     \
            float v_ = fast_tanh(k_[0] + bias_v);                              \
            if (t_ >= len_v) v_ = 0.0f;                                        \
            *outp = v_;                                                        \
            outp += DEPTH * H_DIM;                                             \
            hown[tsH_] = v_;                                                   \
            if (t_ <= T - 2) {                                                 \
                _Pragma("unroll") for (int jj = 0; jj < 3; jj++)               \
                    st_async_f32(hpd[jj] + tsB_, v_, hpm[jj] + 8u * (P));      \
            }                                                                  \
            if (layer < DEPTH - 1) {                                           \
                _Pragma("unroll") for (int q = 0; q < 4; q++)                  \
                    st_async_f32(ipd[q] + tsB_, v_, ipm[q] + 8u * (P));        \
            }                                                                  \
        }                                                                      \
    }                                                                          \
    __syncthreads();                                                           \
    if ((I) <= T && tid < CL_SZ) arrive_mapped(ab + 8u * (P));                 \
} while (0)

    for (int i2 = 0; i2 <= T; i2 += 2) {
        ITER(i2,     0, pm ^ 1);
        ITER(i2 + 1, 1, pm);
        pm ^= 1;
    }
#undef ITER

    // terminal: no CTA exits while peers may still push/arrive into it
    asm volatile("barrier.cluster.arrive.aligned;" ::: "memory");
    asm volatile("barrier.cluster.wait.aligned;" ::: "memory");
}

extern "C" void kernel_launch(void* const* d_in, const int* in_sizes, int n_in,
                              void* d_out, int out_size) {
    const float* x    = (const float*)d_in[0];
    const int*   seq  = (const int*)  d_in[1];
    const float* W_ih = (const float*)d_in[2];
    const float* W_hh = (const float*)d_in[3];
    const float* bias = (const float*)d_in[4];
    float* out = (float*)d_out;

    const int B = in_sizes[1];                    // 16
    const int T = in_sizes[0] / (B * H_DIM);      // 2048

    cudaFuncSetAttribute(rnn12_kernel,
                         cudaFuncAttributeNonPortableClusterSizeAllowed, 1);

    rnn12_kernel<<<dim3((B / 2) * 4, DEPTH, 1), NTHREADS>>>(x, seq, W_ih, W_hh, bias, out, T);
}